// round 7
// baseline (speedup 1.0000x reference)
#include <cuda_runtime.h>
#include <cuda_bf16.h>
#include <cstdint>

#define N_NODES 50000
#define E_EDGES 600000
#define IN_DIM  256
#define OUT_DIM 128
#define SCALE   1.8f
#define ALPHA   0.15f
#define ONE_MA  0.85f

// ---------------------------------------------------------------- scratch
__device__ float g_h[(size_t)N_NODES * OUT_DIM];
__device__ float g_z[(size_t)N_NODES * OUT_DIM];
__device__ __align__(16) int g_indeg[N_NODES];
__device__ int   g_off[N_NODES + 1];
__device__ int   g_cursor[N_NODES];
__device__ float g_dinv[N_NODES];
__device__ uint2 g_edge[E_EDGES];          // packed (src, weight)

// ---------------------------------------------------------------- helpers
__device__ __forceinline__ uint32_t smem_u32(const void* p) {
    uint32_t a;
    asm("{ .reg .u64 t; cvta.to.shared.u64 t, %1; cvt.u32.u64 %0, t; }" : "=r"(a) : "l"(p));
    return a;
}
__device__ __forceinline__ void ldsm_x4(uint32_t* r, uint32_t addr) {
    asm volatile("ldmatrix.sync.aligned.m8n8.x4.shared.b16 {%0,%1,%2,%3}, [%4];"
                 : "=r"(r[0]), "=r"(r[1]), "=r"(r[2]), "=r"(r[3]) : "r"(addr));
}
__device__ __forceinline__ void mma_bf16(float* c, const uint32_t* a, const uint32_t* b) {
    asm volatile("mma.sync.aligned.m16n8k16.row.col.f32.bf16.bf16.f32 "
                 "{%0,%1,%2,%3}, {%4,%5,%6,%7}, {%8,%9}, {%0,%1,%2,%3};"
                 : "+f"(c[0]), "+f"(c[1]), "+f"(c[2]), "+f"(c[3])
                 : "r"(a[0]), "r"(a[1]), "r"(a[2]), "r"(a[3]), "r"(b[0]), "r"(b[1]));
}
__device__ __forceinline__ void split2(float x, float y,
                                       __nv_bfloat162& hi, __nv_bfloat162& lo) {
    __nv_bfloat16 hx = __float2bfloat16(x), hy = __float2bfloat16(y);
    __nv_bfloat16 lx = __float2bfloat16(x - __bfloat162float(hx));
    __nv_bfloat16 ly = __float2bfloat16(y - __bfloat162float(hy));
    hi = __halves2bfloat162(hx, hy);
    lo = __halves2bfloat162(lx, ly);
}

// ---------------------------------------------------------------- graph-norm build
__global__ void k_deg(const int* __restrict__ ei) {
    int e = (blockIdx.x * blockDim.x + threadIdx.x) * 2;   // E even
    if (e < E_EDGES) {
        int2 c2 = *(const int2*)(ei + E_EDGES + e);
        atomicAdd(&g_indeg[c2.x], 1);
        atomicAdd(&g_indeg[c2.y], 1);
    }
}
// single-block exclusive scan, 4 elems/thread (int4), fused dinv
__global__ void __launch_bounds__(1024) k_scan() {
    __shared__ int wsum[32];
    int lane = threadIdx.x & 31, wid = threadIdx.x >> 5;
    int carry = 0;
    for (int base = 0; base < N_NODES; base += 4096) {
        int i4 = base + threadIdx.x * 4;
        int4 v = make_int4(0, 0, 0, 0);
        if (i4 < N_NODES) v = *(const int4*)(g_indeg + i4);   // N%4==0: full or none
        int vs = v.x + v.y + v.z + v.w;
        int x = vs;
#pragma unroll
        for (int d = 1; d < 32; d <<= 1) {
            int y = __shfl_up_sync(0xFFFFFFFFu, x, d);
            if (lane >= d) x += y;
        }
        if (lane == 31) wsum[wid] = x;
        __syncthreads();
        if (wid == 0) {
            int w = wsum[lane];
#pragma unroll
            for (int d = 1; d < 32; d <<= 1) {
                int y = __shfl_up_sync(0xFFFFFFFFu, w, d);
                if (lane >= d) w += y;
            }
            wsum[lane] = w;
        }
        __syncthreads();
        int excl = x - vs + (wid > 0 ? wsum[wid - 1] : 0) + carry;
        if (i4 < N_NODES) {
            int e0 = excl;
            int e1 = e0 + v.x;
            int e2 = e1 + v.y;
            int e3 = e2 + v.z;
            g_off[i4] = e0;     g_cursor[i4] = e0;
            g_off[i4 + 1] = e1; g_cursor[i4 + 1] = e1;
            g_off[i4 + 2] = e2; g_cursor[i4 + 2] = e2;
            g_off[i4 + 3] = e3; g_cursor[i4 + 3] = e3;
            g_dinv[i4]     = rsqrtf((float)(v.x + 1));
            g_dinv[i4 + 1] = rsqrtf((float)(v.y + 1));
            g_dinv[i4 + 2] = rsqrtf((float)(v.z + 1));
            g_dinv[i4 + 3] = rsqrtf((float)(v.w + 1));
        }
        carry += wsum[31];
        __syncthreads();
    }
    if (threadIdx.x == 0) g_off[N_NODES] = E_EDGES;
}
__global__ void k_place(const int* __restrict__ ei) {
    int e = (blockIdx.x * blockDim.x + threadIdx.x) * 2;   // E even
    if (e < E_EDGES) {
        int2 r2 = *(const int2*)(ei + e);
        int2 c2 = *(const int2*)(ei + E_EDGES + e);
        float dr0 = g_dinv[r2.x], dc0 = g_dinv[c2.x];
        float dr1 = g_dinv[r2.y], dc1 = g_dinv[c2.y];
        int p0 = atomicAdd(&g_cursor[c2.x], 1);
        g_edge[p0] = make_uint2((uint32_t)r2.x, __float_as_uint(dr0 * dc0));
        int p1 = atomicAdd(&g_cursor[c2.y], 1);
        g_edge[p1] = make_uint2((uint32_t)r2.y, __float_as_uint(dr1 * dc1));
    }
}

// ---------------------------------------------------------------- HMMA GEMM
// h = normalize(x @ W^T + b) * SCALE via bf16 2-split (hi*hi + hi*lo + lo*hi),
// split fused into smem staging. CTA 128x128, 8 warps (32m x 64n), m16n8k16.
#define RS 40
__global__ void __launch_bounds__(256) k_gemm_mma(const float* __restrict__ X,
                                                  const float* __restrict__ W,
                                                  const float* __restrict__ B) {
    __shared__ __nv_bfloat16 sAhi[128 * RS], sAlo[128 * RS];
    __shared__ __nv_bfloat16 sBhi[128 * RS], sBlo[128 * RS];
    __shared__ float s_bias[OUT_DIM];
    __shared__ float s_ssq[128][2];

    int tid = threadIdx.x, lane = tid & 31, wid = tid >> 5;
    int warp_m = wid & 3, warp_n = wid >> 2;
    int row0 = blockIdx.x * 128;
    if (tid < OUT_DIM) s_bias[tid] = B[tid];

    uint32_t aAhi = smem_u32(sAhi), aAlo = smem_u32(sAlo);
    uint32_t aBhi = smem_u32(sBhi), aBlo = smem_u32(sBlo);

    float c[2][8][4];
#pragma unroll
    for (int mi = 0; mi < 2; mi++)
#pragma unroll
        for (int nj = 0; nj < 8; nj++)
#pragma unroll
            for (int q = 0; q < 4; q++) c[mi][nj][q] = 0.f;

    uint32_t a_row = lane & 15;
    uint32_t a_kh  = lane >> 4;
    uint32_t b_g   = lane >> 3;
    uint32_t b_ln  = lane & 7;

    for (int step = 0; step < 8; step++) {
        int k0 = step * 32;
        for (int t = tid; t < 1024; t += 256) {
            int r  = t >> 3;
            int cc = (t & 7) << 2;
            int so = r * RS + cc;
            int gr = row0 + r;

            float4 xv = make_float4(0.f, 0.f, 0.f, 0.f);
            if (gr < N_NODES)
                xv = *(const float4*)(X + (size_t)gr * IN_DIM + k0 + cc);
            __nv_bfloat162 h01, h23, l01, l23;
            split2(xv.x, xv.y, h01, l01);
            split2(xv.z, xv.w, h23, l23);
            *(__nv_bfloat162*)(sAhi + so)     = h01;
            *(__nv_bfloat162*)(sAhi + so + 2) = h23;
            *(__nv_bfloat162*)(sAlo + so)     = l01;
            *(__nv_bfloat162*)(sAlo + so + 2) = l23;

            float4 wv = *(const float4*)(W + (size_t)r * IN_DIM + k0 + cc);
            split2(wv.x, wv.y, h01, l01);
            split2(wv.z, wv.w, h23, l23);
            *(__nv_bfloat162*)(sBhi + so)     = h01;
            *(__nv_bfloat162*)(sBhi + so + 2) = h23;
            *(__nv_bfloat162*)(sBlo + so)     = l01;
            *(__nv_bfloat162*)(sBlo + so + 2) = l23;
        }
        __syncthreads();

#pragma unroll
        for (int kk = 0; kk < 32; kk += 16) {
            uint32_t ah[2][4], al[2][4];
#pragma unroll
            for (int mi = 0; mi < 2; mi++) {
                uint32_t off = (uint32_t)(warp_m * 32 + mi * 16 + a_row) * (RS * 2)
                             + (kk + a_kh * 8) * 2;
                ldsm_x4(ah[mi], aAhi + off);
                ldsm_x4(al[mi], aAlo + off);
            }
#pragma unroll
            for (int njp = 0; njp < 4; njp++) {
                uint32_t row = (uint32_t)(warp_n * 64 + njp * 16 + (b_g >> 1) * 8 + b_ln);
                uint32_t off = row * (RS * 2) + (kk + (b_g & 1) * 8) * 2;
                uint32_t bh[4], bl[4];
                ldsm_x4(bh, aBhi + off);
                ldsm_x4(bl, aBlo + off);
#pragma unroll
                for (int mi = 0; mi < 2; mi++) {
                    mma_bf16(c[mi][njp * 2],     ah[mi], bh);
                    mma_bf16(c[mi][njp * 2],     ah[mi], bl);
                    mma_bf16(c[mi][njp * 2],     al[mi], bh);
                    mma_bf16(c[mi][njp * 2 + 1], ah[mi], bh + 2);
                    mma_bf16(c[mi][njp * 2 + 1], ah[mi], bl + 2);
                    mma_bf16(c[mi][njp * 2 + 1], al[mi], bh + 2);
                }
            }
        }
        __syncthreads();
    }

    int qr = lane >> 2;
    int qc = (lane & 3) * 2;
    float sq[2][2] = {{0.f, 0.f}, {0.f, 0.f}};
#pragma unroll
    for (int mi = 0; mi < 2; mi++)
#pragma unroll
        for (int nj = 0; nj < 8; nj++) {
            int colb = warp_n * 64 + nj * 8 + qc;
            float b0 = s_bias[colb], b1 = s_bias[colb + 1];
            c[mi][nj][0] += b0; c[mi][nj][1] += b1;
            c[mi][nj][2] += b0; c[mi][nj][3] += b1;
            sq[mi][0] += c[mi][nj][0] * c[mi][nj][0] + c[mi][nj][1] * c[mi][nj][1];
            sq[mi][1] += c[mi][nj][2] * c[mi][nj][2] + c[mi][nj][3] * c[mi][nj][3];
        }
#pragma unroll
    for (int mi = 0; mi < 2; mi++)
#pragma unroll
        for (int h = 0; h < 2; h++) {
            float v = sq[mi][h];
            v += __shfl_xor_sync(0xFFFFFFFFu, v, 1);
            v += __shfl_xor_sync(0xFFFFFFFFu, v, 2);
            if ((lane & 3) == 0)
                s_ssq[warp_m * 32 + mi * 16 + h * 8 + qr][warp_n] = v;
        }
    __syncthreads();
#pragma unroll
    for (int mi = 0; mi < 2; mi++)
#pragma unroll
        for (int h = 0; h < 2; h++) {
            int rloc = warp_m * 32 + mi * 16 + h * 8 + qr;
            float tot = s_ssq[rloc][0] + s_ssq[rloc][1];
            float s = SCALE / fmaxf(sqrtf(tot), 1e-12f);
            int gr = row0 + rloc;
            if (gr < N_NODES) {
                float* o = g_h + (size_t)gr * OUT_DIM + warp_n * 64 + qc;
#pragma unroll
                for (int nj = 0; nj < 8; nj++) {
                    float2 w2;
                    w2.x = c[mi][nj][h * 2] * s;
                    w2.y = c[mi][nj][h * 2 + 1] * s;
                    *(float2*)(o + nj * 8) = w2;
                }
            }
        }
}

// ---------------------------------------------------------------- gather core
// 4-edge batched accumulation: 4 independent row loads in flight (MLP=4)
__device__ __forceinline__ float4 gather_rows(const float* __restrict__ src,
                                              int e0, int e1, int lane) {
    float4 acc = make_float4(0.f, 0.f, 0.f, 0.f);
    int e = e0;
    for (; e + 3 < e1; e += 4) {
        uint2 ea = g_edge[e],     eb = g_edge[e + 1];
        uint2 ec = g_edge[e + 2], ed = g_edge[e + 3];
        float4 v0 = __ldg((const float4*)(src + (size_t)ea.x * OUT_DIM) + lane);
        float4 v1 = __ldg((const float4*)(src + (size_t)eb.x * OUT_DIM) + lane);
        float4 v2 = __ldg((const float4*)(src + (size_t)ec.x * OUT_DIM) + lane);
        float4 v3 = __ldg((const float4*)(src + (size_t)ed.x * OUT_DIM) + lane);
        float w0 = __uint_as_float(ea.y), w1 = __uint_as_float(eb.y);
        float w2 = __uint_as_float(ec.y), w3 = __uint_as_float(ed.y);
        acc.x += w0 * v0.x + w1 * v1.x + w2 * v2.x + w3 * v3.x;
        acc.y += w0 * v0.y + w1 * v1.y + w2 * v2.y + w3 * v3.y;
        acc.z += w0 * v0.z + w1 * v1.z + w2 * v2.z + w3 * v3.z;
        acc.w += w0 * v0.w + w1 * v1.w + w2 * v2.w + w3 * v3.w;
    }
    for (; e < e1; e++) {
        uint2 ed2 = g_edge[e];
        float w = __uint_as_float(ed2.y);
        float4 v = __ldg((const float4*)(src + (size_t)ed2.x * OUT_DIM) + lane);
        acc.x += w * v.x; acc.y += w * v.y; acc.z += w * v.z; acc.w += w * v.w;
    }
    return acc;
}

// z[n] = 0.85*acc + (0.85*dinv^2 + 0.15)*h[n]
__global__ void __launch_bounds__(256) k_gather1() {
    int n = blockIdx.x * 8 + (threadIdx.x >> 5);
    int lane = threadIdx.x & 31;
    if (n >= N_NODES) return;
    float4 acc = gather_rows(g_h, g_off[n], g_off[n + 1], lane);
    float dn = g_dinv[n];
    float sc = ONE_MA * dn * dn + ALPHA;
    float4 hh = __ldg((const float4*)(g_h + (size_t)n * OUT_DIM) + lane);
    float4 o;
    o.x = ONE_MA * acc.x + sc * hh.x;
    o.y = ONE_MA * acc.y + sc * hh.y;
    o.z = ONE_MA * acc.z + sc * hh.z;
    o.w = ONE_MA * acc.w + sc * hh.w;
    *((float4*)(g_z + (size_t)n * OUT_DIM) + lane) = o;
}

// out[n] = 0.85*(acc_z + dinv^2*z[n]) + 0.15*h[n]
__global__ void __launch_bounds__(256) k_gather2(float* __restrict__ out) {
    int n = blockIdx.x * 8 + (threadIdx.x >> 5);
    int lane = threadIdx.x & 31;
    if (n >= N_NODES) return;
    float4 acc = gather_rows(g_z, g_off[n], g_off[n + 1], lane);
    float dn = g_dinv[n];
    float sw = dn * dn;
    float4 cur = __ldg((const float4*)(g_z + (size_t)n * OUT_DIM) + lane);
    float4 hh  = __ldg((const float4*)(g_h + (size_t)n * OUT_DIM) + lane);
    float4 o;
    o.x = ONE_MA * (acc.x + sw * cur.x) + ALPHA * hh.x;
    o.y = ONE_MA * (acc.y + sw * cur.y) + ALPHA * hh.y;
    o.z = ONE_MA * (acc.z + sw * cur.z) + ALPHA * hh.z;
    o.w = ONE_MA * (acc.w + sw * cur.w) + ALPHA * hh.w;
    *((float4*)(out + (size_t)n * OUT_DIM) + lane) = o;
}

// ----------------------------------------------------------------
extern "C" void kernel_launch(void* const* d_in, const int* in_sizes, int n_in,
                              void* d_out, int out_size) {
    const float* x  = (const float*)d_in[0];
    const int*   ei = (const int*)d_in[1];
    const float* W  = (const float*)d_in[2];
    const float* b  = (const float*)d_in[3];
    float* out = (float*)d_out;

    // one-time side-stream + events + symbol address (host resources only)
    static cudaStream_t s2 = nullptr;
    static cudaEvent_t ev_fork = nullptr, ev_join = nullptr;
    static void* indeg_ptr = nullptr;
    if (s2 == nullptr) {
        cudaStreamCreateWithFlags(&s2, cudaStreamNonBlocking);
        cudaEventCreateWithFlags(&ev_fork, cudaEventDisableTiming);
        cudaEventCreateWithFlags(&ev_join, cudaEventDisableTiming);
        cudaGetSymbolAddress(&indeg_ptr, g_indeg);
    }

    // fork: CSR build on s2, GEMM on the main (capture) stream
    cudaEventRecord(ev_fork, 0);
    cudaStreamWaitEvent(s2, ev_fork, 0);

    cudaMemsetAsync(indeg_ptr, 0, N_NODES * sizeof(int), s2);
    k_deg  <<<(E_EDGES / 2 + 255) / 256, 256, 0, s2>>>(ei);
    k_scan <<<1, 1024, 0, s2>>>();
    k_place<<<(E_EDGES / 2 + 255) / 256, 256, 0, s2>>>(ei);
    cudaEventRecord(ev_join, s2);

    k_gemm_mma<<<(N_NODES + 127) / 128, 256>>>(x, W, b);

    // join: gathers need both the GEMM (g_h) and the CSR build
    cudaStreamWaitEvent(0, ev_join, 0);
    k_gather1<<<(N_NODES + 7) / 8, 256>>>();
    k_gather2<<<(N_NODES + 7) / 8, 256>>>(out);
}

// round 8
// speedup vs baseline: 1.1930x; 1.1930x over previous
#include <cuda_runtime.h>
#include <cuda_bf16.h>
#include <cstdint>

#define N_NODES 50000
#define E_EDGES 600000
#define IN_DIM  256
#define OUT_DIM 128
#define SCALE   1.8f
#define ALPHA   0.15f
#define ONE_MA  0.85f

// ---------------------------------------------------------------- scratch
__device__ float g_h[(size_t)N_NODES * OUT_DIM];
__device__ float g_z[(size_t)N_NODES * OUT_DIM];
__device__ __align__(16) int g_indeg[N_NODES];
__device__ int   g_off[N_NODES + 1];
__device__ int   g_cursor[N_NODES];
__device__ float g_dinv[N_NODES];
__device__ uint2 g_edge[E_EDGES];          // packed (src, weight)
__device__ __nv_bfloat16 g_whi[(size_t)OUT_DIM * IN_DIM];
__device__ __nv_bfloat16 g_wlo[(size_t)OUT_DIM * IN_DIM];

// ---------------------------------------------------------------- helpers
__device__ __forceinline__ uint32_t smem_u32(const void* p) {
    uint32_t a;
    asm("{ .reg .u64 t; cvta.to.shared.u64 t, %1; cvt.u32.u64 %0, t; }" : "=r"(a) : "l"(p));
    return a;
}
__device__ __forceinline__ void ldsm_x4(uint32_t* r, uint32_t addr) {
    asm volatile("ldmatrix.sync.aligned.m8n8.x4.shared.b16 {%0,%1,%2,%3}, [%4];"
                 : "=r"(r[0]), "=r"(r[1]), "=r"(r[2]), "=r"(r[3]) : "r"(addr));
}
__device__ __forceinline__ void mma_bf16(float* c, const uint32_t* a, const uint32_t* b) {
    asm volatile("mma.sync.aligned.m16n8k16.row.col.f32.bf16.bf16.f32 "
                 "{%0,%1,%2,%3}, {%4,%5,%6,%7}, {%8,%9}, {%0,%1,%2,%3};"
                 : "+f"(c[0]), "+f"(c[1]), "+f"(c[2]), "+f"(c[3])
                 : "r"(a[0]), "r"(a[1]), "r"(a[2]), "r"(a[3]), "r"(b[0]), "r"(b[1]));
}
__device__ __forceinline__ void split2(float x, float y,
                                       __nv_bfloat162& hi, __nv_bfloat162& lo) {
    __nv_bfloat16 hx = __float2bfloat16(x), hy = __float2bfloat16(y);
    __nv_bfloat16 lx = __float2bfloat16(x - __bfloat162float(hx));
    __nv_bfloat16 ly = __float2bfloat16(y - __bfloat162float(hy));
    hi = __halves2bfloat162(hx, hy);
    lo = __halves2bfloat162(lx, ly);
}

// ---------------------------------------------------------------- W pre-split
__global__ void k_wsplit(const float* __restrict__ W) {
    int i = blockIdx.x * blockDim.x + threadIdx.x;     // pair index
    if (i * 2 >= OUT_DIM * IN_DIM) return;
    float2 v = ((const float2*)W)[i];
    __nv_bfloat16 hx = __float2bfloat16(v.x), hy = __float2bfloat16(v.y);
    __nv_bfloat16 lx = __float2bfloat16(v.x - __bfloat162float(hx));
    __nv_bfloat16 ly = __float2bfloat16(v.y - __bfloat162float(hy));
    ((__nv_bfloat162*)g_whi)[i] = __halves2bfloat162(hx, hy);
    ((__nv_bfloat162*)g_wlo)[i] = __halves2bfloat162(lx, ly);
}

// ---------------------------------------------------------------- graph-norm build
__global__ void k_deg(const int* __restrict__ ei) {
    int e = (blockIdx.x * blockDim.x + threadIdx.x) * 2;   // E even
    if (e < E_EDGES) {
        int2 c2 = *(const int2*)(ei + E_EDGES + e);
        atomicAdd(&g_indeg[c2.x], 1);
        atomicAdd(&g_indeg[c2.y], 1);
    }
}
// single-block exclusive scan, 4 elems/thread (int4), fused dinv
__global__ void __launch_bounds__(1024) k_scan() {
    __shared__ int wsum[32];
    int lane = threadIdx.x & 31, wid = threadIdx.x >> 5;
    int carry = 0;
    for (int base = 0; base < N_NODES; base += 4096) {
        int i4 = base + threadIdx.x * 4;
        int4 v = make_int4(0, 0, 0, 0);
        if (i4 < N_NODES) v = *(const int4*)(g_indeg + i4);   // N%4==0: full or none
        int vs = v.x + v.y + v.z + v.w;
        int x = vs;
#pragma unroll
        for (int d = 1; d < 32; d <<= 1) {
            int y = __shfl_up_sync(0xFFFFFFFFu, x, d);
            if (lane >= d) x += y;
        }
        if (lane == 31) wsum[wid] = x;
        __syncthreads();
        if (wid == 0) {
            int w = wsum[lane];
#pragma unroll
            for (int d = 1; d < 32; d <<= 1) {
                int y = __shfl_up_sync(0xFFFFFFFFu, w, d);
                if (lane >= d) w += y;
            }
            wsum[lane] = w;
        }
        __syncthreads();
        int excl = x - vs + (wid > 0 ? wsum[wid - 1] : 0) + carry;
        if (i4 < N_NODES) {
            int e0 = excl;
            int e1 = e0 + v.x;
            int e2 = e1 + v.y;
            int e3 = e2 + v.z;
            g_off[i4] = e0;     g_cursor[i4] = e0;
            g_off[i4 + 1] = e1; g_cursor[i4 + 1] = e1;
            g_off[i4 + 2] = e2; g_cursor[i4 + 2] = e2;
            g_off[i4 + 3] = e3; g_cursor[i4 + 3] = e3;
            g_dinv[i4]     = rsqrtf((float)(v.x + 1));
            g_dinv[i4 + 1] = rsqrtf((float)(v.y + 1));
            g_dinv[i4 + 2] = rsqrtf((float)(v.z + 1));
            g_dinv[i4 + 3] = rsqrtf((float)(v.w + 1));
        }
        carry += wsum[31];
        __syncthreads();
    }
    if (threadIdx.x == 0) g_off[N_NODES] = E_EDGES;
}
__global__ void k_place(const int* __restrict__ ei) {
    int e = (blockIdx.x * blockDim.x + threadIdx.x) * 2;   // E even
    if (e < E_EDGES) {
        int2 r2 = *(const int2*)(ei + e);
        int2 c2 = *(const int2*)(ei + E_EDGES + e);
        float dr0 = g_dinv[r2.x], dc0 = g_dinv[c2.x];
        float dr1 = g_dinv[r2.y], dc1 = g_dinv[c2.y];
        int p0 = atomicAdd(&g_cursor[c2.x], 1);
        g_edge[p0] = make_uint2((uint32_t)r2.x, __float_as_uint(dr0 * dc0));
        int p1 = atomicAdd(&g_cursor[c2.y], 1);
        g_edge[p1] = make_uint2((uint32_t)r2.y, __float_as_uint(dr1 * dc1));
    }
}

// ---------------------------------------------------------------- HMMA GEMM
// h = normalize(x @ W^T + b) * SCALE via bf16 2-split (hi*hi + hi*lo + lo*hi).
// A (X) split in-register during staging; B (W) pre-split in global.
// CTA 128x128, 8 warps (32m x 64n), m16n8k16; 2 CTAs/SM.
#define RS 40
__global__ void __launch_bounds__(256, 2) k_gemm_mma(const float* __restrict__ X,
                                                     const float* __restrict__ B) {
    __shared__ __nv_bfloat16 sAhi[128 * RS], sAlo[128 * RS];
    __shared__ __nv_bfloat16 sBhi[128 * RS], sBlo[128 * RS];
    __shared__ float s_bias[OUT_DIM];
    __shared__ float s_ssq[128][2];

    int tid = threadIdx.x, lane = tid & 31, wid = tid >> 5;
    int warp_m = wid & 3, warp_n = wid >> 2;
    int row0 = blockIdx.x * 128;
    if (tid < OUT_DIM) s_bias[tid] = B[tid];

    uint32_t aAhi = smem_u32(sAhi), aAlo = smem_u32(sAlo);
    uint32_t aBhi = smem_u32(sBhi), aBlo = smem_u32(sBlo);

    float c[2][8][4];
#pragma unroll
    for (int mi = 0; mi < 2; mi++)
#pragma unroll
        for (int nj = 0; nj < 8; nj++)
#pragma unroll
            for (int q = 0; q < 4; q++) c[mi][nj][q] = 0.f;

    uint32_t a_row = lane & 15;
    uint32_t a_kh  = lane >> 4;
    uint32_t b_g   = lane >> 3;
    uint32_t b_ln  = lane & 7;

    for (int step = 0; step < 8; step++) {
        int k0 = step * 32;
        for (int t = tid; t < 1024; t += 256) {
            int r  = t >> 3;
            int cc = (t & 7) << 2;
            int so = r * RS + cc;
            int gr = row0 + r;

            float4 xv = make_float4(0.f, 0.f, 0.f, 0.f);
            if (gr < N_NODES)
                xv = *(const float4*)(X + (size_t)gr * IN_DIM + k0 + cc);
            __nv_bfloat162 h01, h23, l01, l23;
            split2(xv.x, xv.y, h01, l01);
            split2(xv.z, xv.w, h23, l23);
            *(__nv_bfloat162*)(sAhi + so)     = h01;
            *(__nv_bfloat162*)(sAhi + so + 2) = h23;
            *(__nv_bfloat162*)(sAlo + so)     = l01;
            *(__nv_bfloat162*)(sAlo + so + 2) = l23;

            // B: pre-split, pure copy
            *(uint2*)(sBhi + so) = *(const uint2*)(g_whi + (size_t)r * IN_DIM + k0 + cc);
            *(uint2*)(sBlo + so) = *(const uint2*)(g_wlo + (size_t)r * IN_DIM + k0 + cc);
        }
        __syncthreads();

#pragma unroll
        for (int kk = 0; kk < 32; kk += 16) {
            uint32_t ah[2][4], al[2][4];
#pragma unroll
            for (int mi = 0; mi < 2; mi++) {
                uint32_t off = (uint32_t)(warp_m * 32 + mi * 16 + a_row) * (RS * 2)
                             + (kk + a_kh * 8) * 2;
                ldsm_x4(ah[mi], aAhi + off);
                ldsm_x4(al[mi], aAlo + off);
            }
#pragma unroll
            for (int njp = 0; njp < 4; njp++) {
                uint32_t row = (uint32_t)(warp_n * 64 + njp * 16 + (b_g >> 1) * 8 + b_ln);
                uint32_t off = row * (RS * 2) + (kk + (b_g & 1) * 8) * 2;
                uint32_t bh[4], bl[4];
                ldsm_x4(bh, aBhi + off);
                ldsm_x4(bl, aBlo + off);
#pragma unroll
                for (int mi = 0; mi < 2; mi++) {
                    mma_bf16(c[mi][njp * 2],     ah[mi], bh);
                    mma_bf16(c[mi][njp * 2],     ah[mi], bl);
                    mma_bf16(c[mi][njp * 2],     al[mi], bh);
                    mma_bf16(c[mi][njp * 2 + 1], ah[mi], bh + 2);
                    mma_bf16(c[mi][njp * 2 + 1], ah[mi], bl + 2);
                    mma_bf16(c[mi][njp * 2 + 1], al[mi], bh + 2);
                }
            }
        }
        __syncthreads();
    }

    int qr = lane >> 2;
    int qc = (lane & 3) * 2;
    float sq[2][2] = {{0.f, 0.f}, {0.f, 0.f}};
#pragma unroll
    for (int mi = 0; mi < 2; mi++)
#pragma unroll
        for (int nj = 0; nj < 8; nj++) {
            int colb = warp_n * 64 + nj * 8 + qc;
            float b0 = s_bias[colb], b1 = s_bias[colb + 1];
            c[mi][nj][0] += b0; c[mi][nj][1] += b1;
            c[mi][nj][2] += b0; c[mi][nj][3] += b1;
            sq[mi][0] += c[mi][nj][0] * c[mi][nj][0] + c[mi][nj][1] * c[mi][nj][1];
            sq[mi][1] += c[mi][nj][2] * c[mi][nj][2] + c[mi][nj][3] * c[mi][nj][3];
        }
#pragma unroll
    for (int mi = 0; mi < 2; mi++)
#pragma unroll
        for (int h = 0; h < 2; h++) {
            float v = sq[mi][h];
            v += __shfl_xor_sync(0xFFFFFFFFu, v, 1);
            v += __shfl_xor_sync(0xFFFFFFFFu, v, 2);
            if ((lane & 3) == 0)
                s_ssq[warp_m * 32 + mi * 16 + h * 8 + qr][warp_n] = v;
        }
    __syncthreads();
#pragma unroll
    for (int mi = 0; mi < 2; mi++)
#pragma unroll
        for (int h = 0; h < 2; h++) {
            int rloc = warp_m * 32 + mi * 16 + h * 8 + qr;
            float tot = s_ssq[rloc][0] + s_ssq[rloc][1];
            float s = SCALE / fmaxf(sqrtf(tot), 1e-12f);
            int gr = row0 + rloc;
            if (gr < N_NODES) {
                float* o = g_h + (size_t)gr * OUT_DIM + warp_n * 64 + qc;
#pragma unroll
                for (int nj = 0; nj < 8; nj++) {
                    float2 w2;
                    w2.x = c[mi][nj][h * 2] * s;
                    w2.y = c[mi][nj][h * 2 + 1] * s;
                    *(float2*)(o + nj * 8) = w2;
                }
            }
        }
}

// ---------------------------------------------------------------- gather rounds (R6 form)
__global__ void __launch_bounds__(256) k_gather1() {
    int n = blockIdx.x * 8 + (threadIdx.x >> 5);
    int lane = threadIdx.x & 31;
    if (n >= N_NODES) return;

    int e0 = g_off[n], e1 = g_off[n + 1];
    float4 acc = make_float4(0.f, 0.f, 0.f, 0.f);
#pragma unroll 2
    for (int e = e0; e < e1; e++) {
        uint2 ed = g_edge[e];
        float w = __uint_as_float(ed.y);
        float4 v = __ldg((const float4*)(g_h + (size_t)ed.x * OUT_DIM) + lane);
        acc.x += w * v.x; acc.y += w * v.y; acc.z += w * v.z; acc.w += w * v.w;
    }
    float dn = g_dinv[n];
    float sc = ONE_MA * dn * dn + ALPHA;
    float4 hh = __ldg((const float4*)(g_h + (size_t)n * OUT_DIM) + lane);
    float4 o;
    o.x = ONE_MA * acc.x + sc * hh.x;
    o.y = ONE_MA * acc.y + sc * hh.y;
    o.z = ONE_MA * acc.z + sc * hh.z;
    o.w = ONE_MA * acc.w + sc * hh.w;
    *((float4*)(g_z + (size_t)n * OUT_DIM) + lane) = o;
}

__global__ void __launch_bounds__(256) k_gather2(float* __restrict__ out) {
    int n = blockIdx.x * 8 + (threadIdx.x >> 5);
    int lane = threadIdx.x & 31;
    if (n >= N_NODES) return;

    int e0 = g_off[n], e1 = g_off[n + 1];
    float4 acc = make_float4(0.f, 0.f, 0.f, 0.f);
#pragma unroll 2
    for (int e = e0; e < e1; e++) {
        uint2 ed = g_edge[e];
        float w = __uint_as_float(ed.y);
        float4 v = __ldg((const float4*)(g_z + (size_t)ed.x * OUT_DIM) + lane);
        acc.x += w * v.x; acc.y += w * v.y; acc.z += w * v.z; acc.w += w * v.w;
    }
    float dn = g_dinv[n];
    float sw = dn * dn;
    float4 cur = __ldg((const float4*)(g_z + (size_t)n * OUT_DIM) + lane);
    float4 hh  = __ldg((const float4*)(g_h + (size_t)n * OUT_DIM) + lane);
    float4 o;
    o.x = ONE_MA * (acc.x + sw * cur.x) + ALPHA * hh.x;
    o.y = ONE_MA * (acc.y + sw * cur.y) + ALPHA * hh.y;
    o.z = ONE_MA * (acc.z + sw * cur.z) + ALPHA * hh.z;
    o.w = ONE_MA * (acc.w + sw * cur.w) + ALPHA * hh.w;
    *((float4*)(out + (size_t)n * OUT_DIM) + lane) = o;
}

// ----------------------------------------------------------------
extern "C" void kernel_launch(void* const* d_in, const int* in_sizes, int n_in,
                              void* d_out, int out_size) {
    const float* x  = (const float*)d_in[0];
    const int*   ei = (const int*)d_in[1];
    const float* W  = (const float*)d_in[2];
    const float* b  = (const float*)d_in[3];
    float* out = (float*)d_out;

    // one-time side-stream + events + symbol address (host resources only)
    static cudaStream_t s2 = nullptr;
    static cudaEvent_t ev_fork = nullptr, ev_join = nullptr;
    static void* indeg_ptr = nullptr;
    if (s2 == nullptr) {
        cudaStreamCreateWithFlags(&s2, cudaStreamNonBlocking);
        cudaEventCreateWithFlags(&ev_fork, cudaEventDisableTiming);
        cudaEventCreateWithFlags(&ev_join, cudaEventDisableTiming);
        cudaGetSymbolAddress(&indeg_ptr, g_indeg);
    }

    // fork: CSR build on s2, W-split + GEMM on the main (capture) stream
    cudaEventRecord(ev_fork, 0);
    cudaStreamWaitEvent(s2, ev_fork, 0);

    cudaMemsetAsync(indeg_ptr, 0, N_NODES * sizeof(int), s2);
    k_deg  <<<(E_EDGES / 2 + 255) / 256, 256, 0, s2>>>(ei);
    k_scan <<<1, 1024, 0, s2>>>();
    k_place<<<(E_EDGES / 2 + 255) / 256, 256, 0, s2>>>(ei);
    cudaEventRecord(ev_join, s2);

    k_wsplit<<<(OUT_DIM * IN_DIM / 2 + 255) / 256, 256>>>(W);
    k_gemm_mma<<<(N_NODES + 127) / 128, 256>>>(x, b);

    // join: gathers need both the GEMM (g_h) and the CSR build
    cudaStreamWaitEvent(0, ev_join, 0);
    k_gather1<<<(N_NODES + 7) / 8, 256>>>();
    k_gather2<<<(N_NODES + 7) / 8, 256>>>(out);
}